// round 6
// baseline (speedup 1.0000x reference)
#include <cuda_runtime.h>
#include <cuda_bf16.h>
#include <math.h>
#include <stdint.h>

#define NTOK 2048
#define BATCH 2
#define DIMV 768
#define NHEAD 12
#define HDIM 64
#define KNN 32
#define DFF 3072
#define MROWS 4096   // BATCH*NTOK

// ---------------------------------------------------------------------------
// scratch (uint32 words)
#define W_HH   ((size_t)MROWS * 384)        // packed activation (768/2)
#define W_QKV  ((size_t)MROWS * 2304)       // fused qkv fp32
#define W_X2   ((size_t)MROWS * 768)
#define W_FFN  ((size_t)MROWS * 1536)       // packed ffn (3072/2)
#define W_WQKV ((size_t)2304 * 384)
#define W_WO   ((size_t)768 * 384)
#define W_W1T  ((size_t)3072 * 384)
#define W_W2T  ((size_t)768 * 1536)
#define TOTAL_WORDS (2*W_HH + W_QKV + 2*W_HH + W_X2 + 2*W_HH + 2*W_FFN \
                     + 2*W_WQKV + 2*W_WO + 2*W_W1T + 2*W_W2T + 2304)
__device__ uint32_t g_buf[TOTAL_WORDS];
__device__ int   g_idx[MROWS * KNN];
__device__ float g_dist[MROWS * KNN];

// ---------------------------------------------------------------------------
__device__ __forceinline__ void pack_pair(float x, float y, uint32_t& whi, uint32_t& wlo) {
    __nv_bfloat16 hx = __float2bfloat16_rn(x);
    __nv_bfloat16 hy = __float2bfloat16_rn(y);
    float rx = x - __bfloat162float(hx);
    float ry = y - __bfloat162float(hy);
    __nv_bfloat16 lx = __float2bfloat16_rn(rx);
    __nv_bfloat16 ly = __float2bfloat16_rn(ry);
    whi = (uint32_t)__bfloat16_as_ushort(hx) | ((uint32_t)__bfloat16_as_ushort(hy) << 16);
    wlo = (uint32_t)__bfloat16_as_ushort(lx) | ((uint32_t)__bfloat16_as_ushort(ly) << 16);
}

__device__ __forceinline__ float gelu_f(float v) {
    return 0.5f * v * (1.f + erff(v * 0.70710678118654752f));
}

// ---------------------------------------------------------------------------
// transpose-convert: W[K][Nc] fp32 -> hi/lo packed [Nc][KP] (pairs along K)
__global__ void __launch_bounds__(256) wconvT_kernel(const float* __restrict__ W,
    uint32_t* __restrict__ hi, uint32_t* __restrict__ lo,
    int Nc, int outStride, int rowOff)
{
    __shared__ uint32_t shH[32][33], shL[32][33];
    int tx = threadIdx.x & 31;
    int ty = threadIdx.x >> 5;
    int n0 = blockIdx.x * 32, kp0 = blockIdx.y * 32;
#pragma unroll
    for (int j = 0; j < 4; j++) {
        int kpl = ty * 4 + j, kp = kp0 + kpl;
        float e = W[(size_t)(2 * kp) * Nc + n0 + tx];
        float o = W[(size_t)(2 * kp + 1) * Nc + n0 + tx];
        uint32_t wh, wl; pack_pair(e, o, wh, wl);
        shH[kpl][tx] = wh; shL[kpl][tx] = wl;
    }
    __syncthreads();
#pragma unroll
    for (int j = 0; j < 4; j++) {
        int nl = ty * 4 + j;
        size_t oidx = (size_t)(rowOff + n0 + nl) * outStride + kp0 + tx;
        hi[oidx] = shH[tx][nl];
        lo[oidx] = shL[tx][nl];
    }
}

__global__ void bcat_kernel(const float* __restrict__ a, const float* __restrict__ b,
                            const float* __restrict__ c, float* __restrict__ o)
{
    int i = blockIdx.x * 256 + threadIdx.x;
    if (i >= 2304) return;
    o[i] = (i < 768) ? a[i] : (i < 1536 ? b[i - 768] : c[i - 1536]);
}

// ---------------------------------------------------------------------------
// LayerNorm (+time emb) -> packed bf16 hi/lo
__global__ void __launch_bounds__(384) ln_pack_kernel(const float* __restrict__ x,
    const float* __restrict__ g, const float* __restrict__ be,
    const float* __restrict__ temb, uint32_t* __restrict__ ohi, uint32_t* __restrict__ olo)
{
    __shared__ float sb[13];
    int row = blockIdx.x, tid = threadIdx.x;
    int lane = tid & 31, w = tid >> 5;
    float2 xv = *(const float2*)(x + (size_t)row * DIMV + 2 * tid);
    float s = xv.x + xv.y;
#pragma unroll
    for (int o = 16; o; o >>= 1) s += __shfl_xor_sync(0xffffffffu, s, o);
    if (lane == 0) sb[w] = s;
    __syncthreads();
    if (w == 0) {
        float r = (lane < 12) ? sb[lane] : 0.f;
#pragma unroll
        for (int o = 16; o; o >>= 1) r += __shfl_xor_sync(0xffffffffu, r, o);
        if (lane == 0) sb[12] = r;
    }
    __syncthreads();
    float mu = sb[12] * (1.0f / DIMV);
    float dx = xv.x - mu, dy = xv.y - mu;
    float vs = dx * dx + dy * dy;
    __syncthreads();
#pragma unroll
    for (int o = 16; o; o >>= 1) vs += __shfl_xor_sync(0xffffffffu, vs, o);
    if (lane == 0) sb[w] = vs;
    __syncthreads();
    if (w == 0) {
        float r = (lane < 12) ? sb[lane] : 0.f;
#pragma unroll
        for (int o = 16; o; o >>= 1) r += __shfl_xor_sync(0xffffffffu, r, o);
        if (lane == 0) sb[12] = r;
    }
    __syncthreads();
    float inv = rsqrtf(sb[12] * (1.0f / DIMV) + 1e-5f);
    int b = row >> 11;
    int i0 = 2 * tid;
    float o0 = dx * inv * g[i0] + be[i0];
    float o1 = dy * inv * g[i0 + 1] + be[i0 + 1];
    if (temb) { o0 += temb[b * DIMV + i0]; o1 += temb[b * DIMV + i0 + 1]; }
    uint32_t wh, wl;
    pack_pair(o0, o1, wh, wl);
    ohi[(size_t)row * 384 + tid] = wh;
    olo[(size_t)row * 384 + tid] = wl;
}

// ---------------------------------------------------------------------------
// bf16 mma.sync GEMM, 3-pass hi/lo, ldmatrix fragments, 2 CTAs/SM.
// A packed [M][KP], B packed [Nc][KP]. Tile 128x128, BK=32, 3-stage cp.async,
// single __syncthreads per K-iter.
// ---------------------------------------------------------------------------
#define S_AHI 0
#define S_ALO 2048
#define S_BHI 4096
#define S_BLO 6144
#define STG_WORDS 8192                 // 32KB per stage
#define GEMM_SMEM (3 * STG_WORDS * 4)  // 96KB

__device__ __forceinline__ void cp16s(uint32_t sdst, const uint32_t* src) {
    asm volatile("cp.async.cg.shared.global [%0], [%1], 16;" :: "r"(sdst), "l"(src));
}

#define LDSM4(r, addr)                                                        \
    asm volatile("ldmatrix.sync.aligned.m8n8.x4.shared.b16 {%0,%1,%2,%3}, [%4];" \
        : "=r"((r)[0]), "=r"((r)[1]), "=r"((r)[2]), "=r"((r)[3]) : "r"(addr))

#define MMA16816(d, a, b0, b1)                                                \
    asm volatile(                                                             \
        "mma.sync.aligned.m16n8k16.row.col.f32.bf16.bf16.f32 "                \
        "{%0,%1,%2,%3},{%4,%5,%6,%7},{%8,%9},{%0,%1,%2,%3};"                  \
        : "+f"(d[0]), "+f"(d[1]), "+f"(d[2]), "+f"(d[3])                      \
        : "r"((a)[0]), "r"((a)[1]), "r"((a)[2]), "r"((a)[3]), "r"(b0), "r"(b1))

__global__ void __launch_bounds__(256, 2) tc_gemm_kernel(
    const uint32_t* __restrict__ Ahi, const uint32_t* __restrict__ Alo,
    const uint32_t* __restrict__ Bhi, const uint32_t* __restrict__ Blo,
    const float* __restrict__ bias, const float* __restrict__ res,
    float* __restrict__ Cf, uint32_t* __restrict__ Chi, uint32_t* __restrict__ Clo,
    int Nc, int K, int act)
{
    extern __shared__ __align__(128) uint32_t smw[];
    const int tid = threadIdx.x;
    const int warp = tid >> 5, lane = tid & 31;
    const int wm = warp & 1, wn = warp >> 1;          // warp tile 64x32
    const int g = lane >> 2, t = lane & 3;
    const int bm = blockIdx.y * 128, bn = blockIdx.x * 128;
    const int KP = K >> 1;
    const int nk = K >> 5;                            // BK=32 -> 16 words

    uint32_t sbase;
    asm("{ .reg .u64 tt; cvta.to.shared.u64 tt, %1; cvt.u32.u64 %0, tt; }"
        : "=r"(sbase) : "l"(smw));

    // ---- per-lane ldmatrix byte offsets (within a sub-buffer)
    const int arl = lane & 15, aqb = lane >> 4;
    const int arsw = (arl >> 1) & 3;
    uint32_t aoff[4], aq[2];
#pragma unroll
    for (int mi = 0; mi < 4; mi++)
        aoff[mi] = (uint32_t)(wm * 64 + mi * 16 + arl) * 64u;
#pragma unroll
    for (int kk = 0; kk < 2; kk++)
        aq[kk] = (uint32_t)(((2 * kk + aqb) ^ arsw) << 4);
    const int nrl = (lane & 7) + ((lane >> 4) << 3);
    const int bqb = (lane >> 3) & 1;
    const int brsw = (nrl >> 1) & 3;
    uint32_t boff[2], bq[2];
#pragma unroll
    for (int nh = 0; nh < 2; nh++)
        boff[nh] = (uint32_t)(wn * 32 + nh * 16 + nrl) * 64u;
#pragma unroll
    for (int kk = 0; kk < 2; kk++)
        bq[kk] = (uint32_t)(((2 * kk + bqb) ^ brsw) << 4);

    float acc[4][4][4];
#pragma unroll
    for (int mi = 0; mi < 4; mi++)
#pragma unroll
        for (int ni = 0; ni < 4; ni++)
#pragma unroll
            for (int e = 0; e < 4; e++) acc[mi][ni][e] = 0.f;

    // ---- stage loader: 8 cp.async x 16B per thread
    auto load_stage = [&](int buf, int it) {
        if (it < nk) {
            uint32_t st = sbase + buf * (STG_WORDS * 4);
            int kp0 = it * 16;
#pragma unroll
            for (int r2 = 0; r2 < 2; r2++) {
                int idx = tid + r2 * 256;
                int m = idx >> 2, q = idx & 3;
                uint32_t woff = (uint32_t)(m * 64 + ((q ^ ((m >> 1) & 3)) << 4));
                size_t ga = (size_t)(bm + m) * KP + kp0 + q * 4;
                cp16s(st + S_AHI * 4 + woff, Ahi + ga);
                cp16s(st + S_ALO * 4 + woff, Alo + ga);
                size_t gb = (size_t)(bn + m) * KP + kp0 + q * 4;
                cp16s(st + S_BHI * 4 + woff, Bhi + gb);
                cp16s(st + S_BLO * 4 + woff, Blo + gb);
            }
        }
        asm volatile("cp.async.commit_group;");
    };

    load_stage(0, 0);
    load_stage(1, 1);

    int slot = 0;             // compute slot for iter it (= it % 3)
    int fslot = 2;            // fill slot (= (it+2) % 3)
    for (int it = 0; it < nk; it++) {
        asm volatile("cp.async.wait_group 1;");
        __syncthreads();
        // fill the slot freed by iter it-1 (all warps passed the sync above)
        load_stage(fslot, it + 2);

        uint32_t st = sbase + slot * (STG_WORDS * 4);
#pragma unroll
        for (int kk = 0; kk < 2; kk++) {
            uint32_t Ah[4][4], Al[4][4], Bb[2][4];
#pragma unroll
            for (int mi = 0; mi < 4; mi++)
                LDSM4(Ah[mi], st + S_AHI * 4 + aoff[mi] + aq[kk]);
#pragma unroll
            for (int nh = 0; nh < 2; nh++)
                LDSM4(Bb[nh], st + S_BHI * 4 + boff[nh] + bq[kk]);
            // pass 1: Ahi x Bhi
#pragma unroll
            for (int mi = 0; mi < 4; mi++)
#pragma unroll
                for (int ni = 0; ni < 4; ni++)
                    MMA16816(acc[mi][ni], Ah[mi], Bb[ni >> 1][(ni & 1) * 2],
                             Bb[ni >> 1][(ni & 1) * 2 + 1]);
            // pass 2: Alo x Bhi
#pragma unroll
            for (int mi = 0; mi < 4; mi++)
                LDSM4(Al[mi], st + S_ALO * 4 + aoff[mi] + aq[kk]);
#pragma unroll
            for (int mi = 0; mi < 4; mi++)
#pragma unroll
                for (int ni = 0; ni < 4; ni++)
                    MMA16816(acc[mi][ni], Al[mi], Bb[ni >> 1][(ni & 1) * 2],
                             Bb[ni >> 1][(ni & 1) * 2 + 1]);
            // pass 3: Ahi x Blo
#pragma unroll
            for (int nh = 0; nh < 2; nh++)
                LDSM4(Bb[nh], st + S_BLO * 4 + boff[nh] + bq[kk]);
#pragma unroll
            for (int mi = 0; mi < 4; mi++)
#pragma unroll
                for (int ni = 0; ni < 4; ni++)
                    MMA16816(acc[mi][ni], Ah[mi], Bb[ni >> 1][(ni & 1) * 2],
                             Bb[ni >> 1][(ni & 1) * 2 + 1]);
        }
        slot = (slot == 2) ? 0 : slot + 1;
        fslot = (fslot == 2) ? 0 : fslot + 1;
    }

    // ---- epilogue straight from accumulators
#pragma unroll
    for (int mi = 0; mi < 4; mi++) {
        int r0 = bm + wm * 64 + mi * 16 + g;
#pragma unroll
        for (int ni = 0; ni < 4; ni++) {
            int col = bn + wn * 32 + ni * 8 + 2 * t;
            float bx = bias[col], by = bias[col + 1];
#pragma unroll
            for (int hh = 0; hh < 2; hh++) {
                int r = r0 + hh * 8;
                float vx = acc[mi][ni][2 * hh + 0] + bx;
                float vy = acc[mi][ni][2 * hh + 1] + by;
                if (act) { vx = gelu_f(vx); vy = gelu_f(vy); }
                if (Cf) {
                    if (res) {
                        const float2 rr = *(const float2*)(res + (size_t)r * Nc + col);
                        vx += rr.x; vy += rr.y;
                    }
                    float2 o; o.x = vx; o.y = vy;
                    *(float2*)(Cf + (size_t)r * Nc + col) = o;
                } else {
                    uint32_t wh, wl;
                    pack_pair(vx, vy, wh, wl);
                    size_t ci = (size_t)r * (Nc >> 1) + (col >> 1);
                    Chi[ci] = wh; Clo[ci] = wl;
                }
            }
        }
    }
}

// ---------------------------------------------------------------------------
// Poincare distance + top-KNN per row
__global__ void __launch_bounds__(256) topk_kernel(const float* __restrict__ pos,
    const float* __restrict__ cptr, int* __restrict__ idxo, float* __restrict__ disto)
{
    __shared__ float arg[NTOK];
    __shared__ float rv[8];
    __shared__ int ri[8];
    int row = blockIdx.x;
    int b = row >> 11, i = row & (NTOK - 1);
    float c = cptr[0];
    float inv_sqc = rsqrtf(c);
    const float* pb = pos + (size_t)b * NTOK * 2;
    float yx = pb[i * 2], yy = pb[i * 2 + 1];
    float denY = 1.f - c * (yx * yx + yy * yy);
    for (int j = threadIdx.x; j < NTOK; j += 256) {
        float xx = pb[j * 2], xy = pb[j * 2 + 1];
        float dx = xx - yx, dy = xy - yy;
        float num = 2.f * c * (dx * dx + dy * dy);
        float den = (1.f - c * (xx * xx + xy * xy)) * denY;
        arg[j] = fmaxf(1.f + num / (den + 1e-8f), 1.f);
    }
    __syncthreads();
    int lane = threadIdx.x & 31, w = threadIdx.x >> 5;
    for (int sel = 0; sel < KNN; sel++) {
        float bv = 3.4e38f; int bi = 0x7fffffff;
        for (int j = threadIdx.x; j < NTOK; j += 256) {
            float a = arg[j];
            if (a < bv) { bv = a; bi = j; }
        }
#pragma unroll
        for (int o = 16; o; o >>= 1) {
            float ov = __shfl_xor_sync(0xffffffffu, bv, o);
            int   oi = __shfl_xor_sync(0xffffffffu, bi, o);
            if (ov < bv || (ov == bv && oi < bi)) { bv = ov; bi = oi; }
        }
        if (lane == 0) { rv[w] = bv; ri[w] = bi; }
        __syncthreads();
        if (threadIdx.x == 0) {
            float fv = rv[0]; int fi = ri[0];
            for (int t2 = 1; t2 < 8; t2++)
                if (rv[t2] < fv || (rv[t2] == fv && ri[t2] < fi)) { fv = rv[t2]; fi = ri[t2]; }
            idxo[(size_t)row * KNN + sel] = fi;
            disto[(size_t)row * KNN + sel] = acoshf(fv) * inv_sqc;
            arg[fi] = 3.4e38f;
        }
        __syncthreads();
    }
}

// ---------------------------------------------------------------------------
// kNN attention over fused qkv [row][2304]; packed output
__global__ void __launch_bounds__(384) attn_kernel(const float* __restrict__ qkv,
    const int* __restrict__ idx, const float* __restrict__ dist,
    const float* __restrict__ log_tau,
    uint32_t* __restrict__ ohi, uint32_t* __restrict__ olo)
{
    __shared__ int sidx[KNN];
    __shared__ float sgeo[KNN];
    int row = blockIdx.x;
    int lane = threadIdx.x & 31, h = threadIdx.x >> 5;
    float invtau = 1.f / (expf(log_tau[0]) + 1e-8f);
    if (threadIdx.x < KNN) {
        sidx[threadIdx.x] = idx[(size_t)row * KNN + threadIdx.x];
        sgeo[threadIdx.x] = -dist[(size_t)row * KNN + threadIdx.x] * invtau;
    }
    __syncthreads();
    int b = row >> 11;
    const float* qp = qkv + (size_t)row * 2304 + h * HDIM;
    float q0 = qp[2 * lane], q1 = qp[2 * lane + 1];
    const float* kb = qkv + (size_t)b * NTOK * 2304 + 768 + h * HDIM;
    const float* vb = qkv + (size_t)b * NTOK * 2304 + 1536 + h * HDIM;
    float myscore = 0.f;
#pragma unroll 4
    for (int j = 0; j < KNN; j++) {
        const float* kp = kb + (size_t)sidx[j] * 2304;
        float p = q0 * kp[2 * lane] + q1 * kp[2 * lane + 1];
#pragma unroll
        for (int o = 16; o; o >>= 1) p += __shfl_xor_sync(0xffffffffu, p, o);
        if (lane == j) myscore = p * 0.125f + sgeo[j];
    }
    float m = myscore;
#pragma unroll
    for (int o = 16; o; o >>= 1) m = fmaxf(m, __shfl_xor_sync(0xffffffffu, m, o));
    float e = expf(myscore - m);
    float s = e;
#pragma unroll
    for (int o = 16; o; o >>= 1) s += __shfl_xor_sync(0xffffffffu, s, o);
    float p = e / s;
    float o0 = 0.f, o1 = 0.f;
#pragma unroll 4
    for (int j = 0; j < KNN; j++) {
        float pj = __shfl_sync(0xffffffffu, p, j);
        const float* vp = vb + (size_t)sidx[j] * 2304;
        o0 += pj * vp[2 * lane]; o1 += pj * vp[2 * lane + 1];
    }
    uint32_t wh, wl;
    pack_pair(o0, o1, wh, wl);
    size_t wi = (size_t)row * 384 + h * 32 + lane;
    ohi[wi] = wh; olo[wi] = wl;
}

// ---------------------------------------------------------------------------
extern "C" void kernel_launch(void* const* d_in, const int* in_sizes, int n_in,
                              void* d_out, int out_size)
{
    const float* x    = (const float*)d_in[0];
    const float* pos  = (const float*)d_in[1];
    const float* c    = (const float*)d_in[2];
    const float* temb = (const float*)d_in[3];
    const float* Wq = (const float*)d_in[4],  *bq = (const float*)d_in[5];
    const float* Wk = (const float*)d_in[6],  *bk = (const float*)d_in[7];
    const float* Wv = (const float*)d_in[8],  *bv = (const float*)d_in[9];
    const float* Wo = (const float*)d_in[10], *bo = (const float*)d_in[11];
    const float* W1 = (const float*)d_in[12], *b1 = (const float*)d_in[13];
    const float* W2 = (const float*)d_in[14], *b2 = (const float*)d_in[15];
    const float* g1 = (const float*)d_in[16], *be1 = (const float*)d_in[17];
    const float* g2 = (const float*)d_in[18], *be2 = (const float*)d_in[19];
    const float* log_tau = (const float*)d_in[20];
    float* out = (float*)d_out;

    uint32_t* base; cudaGetSymbolAddress((void**)&base, g_buf);
    int* idxp;      cudaGetSymbolAddress((void**)&idxp, g_idx);
    float* distp;   cudaGetSymbolAddress((void**)&distp, g_dist);

    uint32_t* p = base;
    uint32_t *hHi = p; p += W_HH;  uint32_t *hLo = p; p += W_HH;
    float *qkv = (float*)p; p += W_QKV;
    uint32_t *attHi = p; p += W_HH; uint32_t *attLo = p; p += W_HH;
    float *x2 = (float*)p; p += W_X2;
    uint32_t *h2Hi = p; p += W_HH; uint32_t *h2Lo = p; p += W_HH;
    uint32_t *ffnHi = p; p += W_FFN; uint32_t *ffnLo = p; p += W_FFN;
    uint32_t *WqkvHi = p; p += W_WQKV; uint32_t *WqkvLo = p; p += W_WQKV;
    uint32_t *WoHi = p; p += W_WO; uint32_t *WoLo = p; p += W_WO;
    uint32_t *W1Hi = p; p += W_W1T; uint32_t *W1Lo = p; p += W_W1T;
    uint32_t *W2Hi = p; p += W_W2T; uint32_t *W2Lo = p; p += W_W2T;
    float *bqkv = (float*)p; p += 2304;

    cudaFuncSetAttribute(tc_gemm_kernel,
                         cudaFuncAttributeMaxDynamicSharedMemorySize, GEMM_SMEM);

    // launches 1-5 (so ncu -s 5 -c 1 captures the fused-QKV GEMM as launch #6)
    wconvT_kernel<<<dim3(24, 12), 256>>>(Wq, WqkvHi, WqkvLo, 768, 384, 0);
    wconvT_kernel<<<dim3(24, 12), 256>>>(Wk, WqkvHi, WqkvLo, 768, 384, 768);
    wconvT_kernel<<<dim3(24, 12), 256>>>(Wv, WqkvHi, WqkvLo, 768, 384, 1536);
    bcat_kernel<<<9, 256>>>(bq, bk, bv, bqkv);
    ln_pack_kernel<<<MROWS, 384>>>(x, g1, be1, temb, hHi, hLo);

    // launch 6: fused QKV [4096,768] @ [768,2304]
    tc_gemm_kernel<<<dim3(18, 32), 256, GEMM_SMEM>>>(hHi, hLo, WqkvHi, WqkvLo,
        bqkv, nullptr, qkv, nullptr, nullptr, 2304, 768, 0);

    topk_kernel<<<MROWS, 256>>>(pos, c, idxp, distp);
    attn_kernel<<<MROWS, 384>>>(qkv, idxp, distp, log_tau, attHi, attLo);

    // remaining weight conversions (after QKV so the profile slot stays fixed)
    wconvT_kernel<<<dim3(24, 12), 256>>>(Wo, WoHi, WoLo, 768, 384, 0);
    wconvT_kernel<<<dim3(96, 12), 256>>>(W1, W1Hi, W1Lo, 3072, 384, 0);
    wconvT_kernel<<<dim3(24, 48), 256>>>(W2, W2Hi, W2Lo, 768, 1536, 0);

    // x2 = x + att @ Wo
    tc_gemm_kernel<<<dim3(6, 32), 256, GEMM_SMEM>>>(attHi, attLo, WoHi, WoLo,
        bo, x, x2, nullptr, nullptr, 768, 768, 0);
    ln_pack_kernel<<<MROWS, 384>>>(x2, g2, be2, nullptr, h2Hi, h2Lo);

    // ffn = gelu(h2 @ W1)  (packed out)
    tc_gemm_kernel<<<dim3(24, 32), 256, GEMM_SMEM>>>(h2Hi, h2Lo, W1Hi, W1Lo,
        b1, nullptr, nullptr, ffnHi, ffnLo, 3072, 768, 1);
    // out = x2 + ffn @ W2
    tc_gemm_kernel<<<dim3(6, 32), 256, GEMM_SMEM>>>(ffnHi, ffnLo, W2Hi, W2Lo,
        b2, x2, out, nullptr, nullptr, 768, 3072, 0);
}